// round 5
// baseline (speedup 1.0000x reference)
#include <cuda_runtime.h>
#include <cuda_bf16.h>
#include <cstdint>

// Shapes: B=4, S=2048, H=D=2048
#define B_ 4
#define S_ 2048
#define H_ 2048
#define M_ (B_ * S_)   // 8192
#define N_ H_
#define K_ H_

// ---------------- scratch (static device arrays, no allocation) -------------
__device__ __nv_bfloat16 g_xkh[(size_t)M_ * H_], g_xkl[(size_t)M_ * H_];
__device__ __nv_bfloat16 g_xvh[(size_t)M_ * H_], g_xvl[(size_t)M_ * H_];
__device__ __nv_bfloat16 g_xrh[(size_t)M_ * H_], g_xrl[(size_t)M_ * H_];
__device__ __nv_bfloat16 g_yh [(size_t)M_ * H_], g_yl [(size_t)M_ * H_];
__device__ __nv_bfloat16 g_wh[4][(size_t)N_ * K_];
__device__ __nv_bfloat16 g_wl[4][(size_t)N_ * K_];
__device__ float g_k[(size_t)M_ * H_];
__device__ float g_v[(size_t)M_ * H_];
__device__ float g_r[(size_t)M_ * H_];

// ---------------- helpers ----------------
__device__ __forceinline__ uint32_t smem_u32(const void* p) {
    uint32_t a;
    asm("{ .reg .u64 t; cvta.to.shared.u64 t, %1; cvt.u32.u64 %0, t; }"
        : "=r"(a) : "l"(p));
    return a;
}
__device__ __forceinline__ void cpasync16(uint32_t dst, const void* src) {
    asm volatile("cp.async.cg.shared.global [%0], [%1], 16;" :: "r"(dst), "l"(src));
}
__device__ __forceinline__ void cp_commit() {
    asm volatile("cp.async.commit_group;" ::: "memory");
}
template <int N> __device__ __forceinline__ void cp_wait() {
    asm volatile("cp.async.wait_group %0;" :: "n"(N) : "memory");
}
__device__ __forceinline__ void ldsm4(uint32_t* r, uint32_t a) {
    asm volatile("ldmatrix.sync.aligned.m8n8.x4.shared.b16 {%0,%1,%2,%3}, [%4];"
                 : "=r"(r[0]), "=r"(r[1]), "=r"(r[2]), "=r"(r[3]) : "r"(a));
}
__device__ __forceinline__ void mma16816(float* c, const uint32_t* a, const uint32_t* b) {
    asm volatile(
        "mma.sync.aligned.m16n8k16.row.col.f32.bf16.bf16.f32 "
        "{%0,%1,%2,%3}, {%4,%5,%6,%7}, {%8,%9}, {%0,%1,%2,%3};"
        : "+f"(c[0]), "+f"(c[1]), "+f"(c[2]), "+f"(c[3])
        : "r"(a[0]), "r"(a[1]), "r"(a[2]), "r"(a[3]), "r"(b[0]), "r"(b[1]));
}
__device__ __forceinline__ void split_bf(float x, __nv_bfloat16& h, __nv_bfloat16& l) {
    h = __float2bfloat16(x);
    l = __float2bfloat16(x - __bfloat162float(h));
}
__device__ __forceinline__ uint32_t swz(uint32_t off) {   // SW128
    return off ^ ((off >> 3) & 0x70);
}

// ============================================================================
// Convert all four W matrices (fp32) to bf16 hi/lo. grid (4096, 4).
// ============================================================================
__global__ void convw_all(const float* __restrict__ W0, const float* __restrict__ W1,
                          const float* __restrict__ W2, const float* __restrict__ W3) {
    const int widx = blockIdx.y;
    const float* W = (widx == 0) ? W0 : (widx == 1) ? W1 : (widx == 2) ? W2 : W3;
    int i = blockIdx.x * blockDim.x + threadIdx.x;   // float4 index
    float4 w = ((const float4*)W)[i];
    __nv_bfloat16 h0, l0, h1, l1, h2, l2, h3, l3;
    split_bf(w.x, h0, l0); split_bf(w.y, h1, l1);
    split_bf(w.z, h2, l2); split_bf(w.w, h3, l3);
    __nv_bfloat162* ph = (__nv_bfloat162*)g_wh[widx];
    __nv_bfloat162* pl = (__nv_bfloat162*)g_wl[widx];
    ph[2 * i]     = __nv_bfloat162(h0, h1);
    ph[2 * i + 1] = __nv_bfloat162(h2, h3);
    pl[2 * i]     = __nv_bfloat162(l0, l1);
    pl[2 * i + 1] = __nv_bfloat162(l2, l3);
}

// ============================================================================
// time-shift mix -> bf16 hi/lo of xk, xv, xr
// ============================================================================
__global__ void mix_kernel(const float* __restrict__ hidden,
                           const float* __restrict__ tmk,
                           const float* __restrict__ tmv,
                           const float* __restrict__ tmr) {
    const int H4 = H_ / 4;
    int i = blockIdx.x * blockDim.x + threadIdx.x;   // float4 index
    int h4  = i % H4;
    int row = i / H4;
    int s   = row & (S_ - 1);

    float4 cur = ((const float4*)hidden)[i];
    float4 sh  = make_float4(0.f, 0.f, 0.f, 0.f);
    if (s != 0) sh = ((const float4*)hidden)[i - H4];

    float4 mk = ((const float4*)tmk)[h4];
    float4 mv = ((const float4*)tmv)[h4];
    float4 mr = ((const float4*)tmr)[h4];

    float dx = cur.x - sh.x, dy = cur.y - sh.y, dz = cur.z - sh.z, dw = cur.w - sh.w;

    float vals[3][4];
    vals[0][0] = fmaf(mk.x, dx, sh.x); vals[0][1] = fmaf(mk.y, dy, sh.y);
    vals[0][2] = fmaf(mk.z, dz, sh.z); vals[0][3] = fmaf(mk.w, dw, sh.w);
    vals[1][0] = fmaf(mv.x, dx, sh.x); vals[1][1] = fmaf(mv.y, dy, sh.y);
    vals[1][2] = fmaf(mv.z, dz, sh.z); vals[1][3] = fmaf(mv.w, dw, sh.w);
    vals[2][0] = fmaf(mr.x, dx, sh.x); vals[2][1] = fmaf(mr.y, dy, sh.y);
    vals[2][2] = fmaf(mr.z, dz, sh.z); vals[2][3] = fmaf(mr.w, dw, sh.w);

    __nv_bfloat162* dh[3] = {(__nv_bfloat162*)g_xkh, (__nv_bfloat162*)g_xvh, (__nv_bfloat162*)g_xrh};
    __nv_bfloat162* dl[3] = {(__nv_bfloat162*)g_xkl, (__nv_bfloat162*)g_xvl, (__nv_bfloat162*)g_xrl};
#pragma unroll
    for (int t = 0; t < 3; ++t) {
        __nv_bfloat16 h0, l0, h1, l1, h2, l2, h3, l3;
        split_bf(vals[t][0], h0, l0); split_bf(vals[t][1], h1, l1);
        split_bf(vals[t][2], h2, l2); split_bf(vals[t][3], h3, l3);
        dh[t][2 * i]     = __nv_bfloat162(h0, h1);
        dh[t][2 * i + 1] = __nv_bfloat162(h2, h3);
        dl[t][2 * i]     = __nv_bfloat162(l0, l1);
        dl[t][2 * i + 1] = __nv_bfloat162(l2, l3);
    }
}

// ============================================================================
// HMMA GEMM, bf16x3 split as virtual K' = 3*2048.
// CTA 128x128, 8 warps (2x4), warp tile 64x32 (m16n8k16).
// BK=64 per stage (128B rows, SW128 swizzle), ldmatrix.x4 fragments,
// 3-stage cp.async pipeline, ONE __syncthreads per stage.
// ============================================================================
#define NST 3
#define BKS 64
#define STGB (128 * 128)                // bytes per matrix per stage
#define NSTEP (3 * K_ / BKS)            // 96

__global__ __launch_bounds__(256) void gemm_hmma(int which, float* __restrict__ Cout) {
    extern __shared__ char sm[];

    const __nv_bfloat16 *Ah, *Al, *Bh, *Bl;
    float* C;
    bool sig = false;
    if (which == 0)      { Ah = g_xkh; Al = g_xkl; Bh = g_wh[0]; Bl = g_wl[0]; C = g_k; }
    else if (which == 1) { Ah = g_xvh; Al = g_xvl; Bh = g_wh[1]; Bl = g_wl[1]; C = g_v; }
    else if (which == 2) { Ah = g_xrh; Al = g_xrl; Bh = g_wh[2]; Bl = g_wl[2]; C = g_r; sig = true; }
    else                 { Ah = g_yh;  Al = g_yl;  Bh = g_wh[3]; Bl = g_wl[3]; C = Cout; }

    const int tid  = threadIdx.x;
    const int wid  = tid >> 5;
    const int lane = tid & 31;
    const int wm   = wid >> 2;      // 0..1
    const int wn   = wid & 3;       // 0..3
    const int g    = lane >> 2;     // 0..7
    const int t4   = lane & 3;      // 0..3

    const int rowA0 = blockIdx.y * 128;
    const int rowB0 = blockIdx.x * 128;

    const uint32_t sA0 = smem_u32(sm);
    const uint32_t sB0 = sA0 + NST * STGB;

    // gmem->smem mapping: 1024 16B-chunks per matrix per stage, 4 per thread
    const int ldr = tid >> 1;               // unused placeholder removed below
    (void)ldr;

    auto load_stage = [&](int st, int slot) {
        int phase = st >> 5;                 // 32 stages per split-phase
        int k0 = (st & 31) * BKS;
        const __nv_bfloat16* Ap = (phase < 2) ? Ah : Al;
        const __nv_bfloat16* Bp = (phase == 1) ? Bl : Bh;
#pragma unroll
        for (int i = 0; i < 4; ++i) {
            int id = i * 256 + tid;          // 0..1023
            int row = id >> 3, c = id & 7;
            uint32_t sw = swz(row * 128 + c * 16);
            cpasync16(sA0 + slot * STGB + sw, Ap + (size_t)(rowA0 + row) * K_ + k0 + c * 8);
        }
#pragma unroll
        for (int i = 0; i < 4; ++i) {
            int id = i * 256 + tid;
            int row = id >> 3, c = id & 7;
            uint32_t sw = swz(row * 128 + c * 16);
            cpasync16(sB0 + slot * STGB + sw, Bp + (size_t)(rowB0 + row) * K_ + k0 + c * 8);
        }
    };

    // per-lane ldmatrix row bases
    const int atsel = lane >> 3;            // 0..3
    const int arin  = lane & 7;
    // A: tiles [m0k0, m8k0, m0k8, m8k8] -> row = (tsel&1)*8 + rin, colb = (tsel>>1)*16
    const int aRowBase = wm * 64 + (atsel & 1) * 8 + arin;
    const int aColBase = (atsel >> 1) * 16;
    // B: tiles [n0k0, n0k8, n8k0, n8k8] -> row = (tsel>>1)*8 + rin, colb = (tsel&1)*16
    const int bRowBase = wn * 32 + (atsel >> 1) * 8 + arin;
    const int bColBase = (atsel & 1) * 16;

    float acc[4][4][4];
#pragma unroll
    for (int i = 0; i < 4; ++i)
#pragma unroll
        for (int j = 0; j < 4; ++j)
#pragma unroll
            for (int r = 0; r < 4; ++r) acc[i][j][r] = 0.f;

    load_stage(0, 0); cp_commit();
    load_stage(1, 1); cp_commit();

    for (int kt = 0; kt < NSTEP; ++kt) {
        const int slot = kt % NST;
        if (kt + 1 < NSTEP) cp_wait<1>(); else cp_wait<0>();
        __syncthreads();

        // issue next stage's loads early (overwrites slot last read at kt-1;
        // the barrier above orders that)
        if (kt + 2 < NSTEP) { load_stage(kt + 2, (kt + 2) % NST); cp_commit(); }

        const uint32_t aBase = sA0 + slot * STGB;
        const uint32_t bBase = sB0 + slot * STGB;

#pragma unroll
        for (int kc = 0; kc < 4; ++kc) {
            uint32_t afr[4][4];
#pragma unroll
            for (int mt = 0; mt < 4; ++mt)
                ldsm4(afr[mt], aBase + swz((aRowBase + mt * 16) * 128 + kc * 32 + aColBase));
            uint32_t bfr[2][4];
#pragma unroll
            for (int np = 0; np < 2; ++np)
                ldsm4(bfr[np], bBase + swz((bRowBase + np * 16) * 128 + kc * 32 + bColBase));
#pragma unroll
            for (int mt = 0; mt < 4; ++mt)
#pragma unroll
                for (int nt = 0; nt < 4; ++nt)
                    mma16816(acc[mt][nt], afr[mt], &bfr[nt >> 1][(nt & 1) * 2]);
        }
    }

    // epilogue
#pragma unroll
    for (int mt = 0; mt < 4; ++mt) {
        size_t row = (size_t)rowA0 + wm * 64 + mt * 16 + g;
#pragma unroll
        for (int nt = 0; nt < 4; ++nt) {
            int col = rowB0 + wn * 32 + nt * 8 + 2 * t4;
            float2 lo = make_float2(acc[mt][nt][0], acc[mt][nt][1]);
            float2 hi = make_float2(acc[mt][nt][2], acc[mt][nt][3]);
            if (sig) {
                lo.x = 1.f / (1.f + __expf(-lo.x)); lo.y = 1.f / (1.f + __expf(-lo.y));
                hi.x = 1.f / (1.f + __expf(-hi.x)); hi.y = 1.f / (1.f + __expf(-hi.y));
            }
            *(float2*)(C + row * N_ + col) = lo;
            *(float2*)(C + (row + 8) * N_ + col) = hi;
        }
    }
}

// ============================================================================
// WKV scan: one thread per (b,d); writes y = r*wkv as bf16 hi/lo
// ============================================================================
__global__ void wkv_kernel(const float* __restrict__ time_decay,
                           const float* __restrict__ time_first) {
    int t = blockIdx.x * blockDim.x + threadIdx.x;
    int b = t >> 11;
    int d = t & (H_ - 1);

    float w  = -__expf(time_decay[d]);
    float tf = time_first[d];

    float num = 0.f, den = 0.f, mx = -1e38f;
    size_t idx = (size_t)b * S_ * H_ + d;

#pragma unroll 2
    for (int s = 0; s < S_; ++s, idx += H_) {
        float k = g_k[idx];
        float v = g_v[idx];
        float r = g_r[idx];

        float ktf = k + tf;
        float mo  = fmaxf(mx, ktf);
        float e1  = __expf(mx - mo);
        float e2  = __expf(ktf - mo);
        float out = __fdividef(e1 * num + e2 * v, e1 * den + e2);
        float y = r * out;
        __nv_bfloat16 h, l;
        split_bf(y, h, l);
        g_yh[idx] = h;
        g_yl[idx] = l;

        float mw  = mx + w;
        float mn  = fmaxf(mw, k);
        float e1n = __expf(mw - mn);
        float e2n = __expf(k - mn);
        num = e1n * num + e2n * v;
        den = e1n * den + e2n;
        mx  = mn;
    }
}

// ============================================================================
// Launch
// ============================================================================
extern "C" void kernel_launch(void* const* d_in, const int* in_sizes, int n_in,
                              void* d_out, int out_size) {
    const float* hidden     = (const float*)d_in[0];
    const float* time_decay = (const float*)d_in[1];
    const float* time_first = (const float*)d_in[2];
    const float* tmk        = (const float*)d_in[3];
    const float* tmv        = (const float*)d_in[4];
    const float* tmr        = (const float*)d_in[5];
    const float* Wk         = (const float*)d_in[6];
    const float* Wv         = (const float*)d_in[7];
    const float* Wr         = (const float*)d_in[8];
    const float* Wo         = (const float*)d_in[9];
    float* out              = (float*)d_out;

    const int shm = 2 * NST * STGB;   // 96 KB
    cudaFuncSetAttribute(gemm_hmma, cudaFuncAttributeMaxDynamicSharedMemorySize, shm);

    // 0) weight conversion to bf16 hi/lo (one launch)
    {
        dim3 g((N_ * K_ / 4) / 256, 4);
        convw_all<<<g, 256>>>(Wk, Wv, Wr, Wo);
    }

    // 1) time-shift mix (fp32 -> bf16 hi/lo)
    mix_kernel<<<(M_ * H_ / 4) / 256, 256>>>(hidden, tmk, tmv, tmr);

    // 2) projection GEMMs
    dim3 gg(N_ / 128, M_ / 128);   // (16, 64)
    gemm_hmma<<<gg, 256, shm>>>(0, nullptr);
    gemm_hmma<<<gg, 256, shm>>>(1, nullptr);
    gemm_hmma<<<gg, 256, shm>>>(2, nullptr);

    // 3) WKV scan (writes y hi/lo)
    wkv_kernel<<<256, 32>>>(time_decay, time_first);

    // 4) output GEMM
    gemm_hmma<<<gg, 256, shm>>>(3, out);
}

// round 6
// speedup vs baseline: 1.9140x; 1.9140x over previous
#include <cuda_runtime.h>
#include <cuda_bf16.h>
#include <cstdint>

// Shapes: B=4, S=2048, H=D=2048
#define B_ 4
#define S_ 2048
#define H_ 2048
#define M_ (B_ * S_)   // 8192
#define N_ H_
#define K_ H_

// ---------------- scratch (static device arrays, no allocation) -------------
__device__ __nv_bfloat16 g_xkh[(size_t)M_ * H_], g_xkl[(size_t)M_ * H_];
__device__ __nv_bfloat16 g_xvh[(size_t)M_ * H_], g_xvl[(size_t)M_ * H_];
__device__ __nv_bfloat16 g_xrh[(size_t)M_ * H_], g_xrl[(size_t)M_ * H_];
__device__ __nv_bfloat16 g_yh [(size_t)M_ * H_], g_yl [(size_t)M_ * H_];
__device__ __nv_bfloat16 g_wh[4][(size_t)N_ * K_];
__device__ __nv_bfloat16 g_wl[4][(size_t)N_ * K_];
__device__ float g_k[(size_t)M_ * H_];
__device__ float g_v[(size_t)M_ * H_];
__device__ float g_r[(size_t)M_ * H_];

// ---------------- helpers ----------------
__device__ __forceinline__ uint32_t smem_u32(const void* p) {
    uint32_t a;
    asm("{ .reg .u64 t; cvta.to.shared.u64 t, %1; cvt.u32.u64 %0, t; }"
        : "=r"(a) : "l"(p));
    return a;
}
__device__ __forceinline__ void cpasync16(uint32_t dst, const void* src) {
    asm volatile("cp.async.cg.shared.global [%0], [%1], 16;" :: "r"(dst), "l"(src));
}
__device__ __forceinline__ void cp_commit() {
    asm volatile("cp.async.commit_group;" ::: "memory");
}
template <int N> __device__ __forceinline__ void cp_wait() {
    asm volatile("cp.async.wait_group %0;" :: "n"(N) : "memory");
}
__device__ __forceinline__ void ldsm4(uint32_t* r, uint32_t a) {
    asm volatile("ldmatrix.sync.aligned.m8n8.x4.shared.b16 {%0,%1,%2,%3}, [%4];"
                 : "=r"(r[0]), "=r"(r[1]), "=r"(r[2]), "=r"(r[3]) : "r"(a));
}
__device__ __forceinline__ void mma16816(float* c, const uint32_t* a, const uint32_t* b) {
    asm volatile(
        "mma.sync.aligned.m16n8k16.row.col.f32.bf16.bf16.f32 "
        "{%0,%1,%2,%3}, {%4,%5,%6,%7}, {%8,%9}, {%0,%1,%2,%3};"
        : "+f"(c[0]), "+f"(c[1]), "+f"(c[2]), "+f"(c[3])
        : "r"(a[0]), "r"(a[1]), "r"(a[2]), "r"(a[3]), "r"(b[0]), "r"(b[1]));
}
__device__ __forceinline__ void split_bf(float x, __nv_bfloat16& h, __nv_bfloat16& l) {
    h = __float2bfloat16(x);
    l = __float2bfloat16(x - __bfloat162float(h));
}
__device__ __forceinline__ uint32_t swz(uint32_t off) {   // SW128
    return off ^ ((off >> 3) & 0x70);
}

// ============================================================================
// Convert all four W matrices (fp32) to bf16 hi/lo. grid (4096, 4).
// ============================================================================
__global__ void convw_all(const float* __restrict__ W0, const float* __restrict__ W1,
                          const float* __restrict__ W2, const float* __restrict__ W3) {
    const int widx = blockIdx.y;
    const float* W = (widx == 0) ? W0 : (widx == 1) ? W1 : (widx == 2) ? W2 : W3;
    int i = blockIdx.x * blockDim.x + threadIdx.x;   // float4 index
    float4 w = ((const float4*)W)[i];
    __nv_bfloat16 h0, l0, h1, l1, h2, l2, h3, l3;
    split_bf(w.x, h0, l0); split_bf(w.y, h1, l1);
    split_bf(w.z, h2, l2); split_bf(w.w, h3, l3);
    __nv_bfloat162* ph = (__nv_bfloat162*)g_wh[widx];
    __nv_bfloat162* pl = (__nv_bfloat162*)g_wl[widx];
    ph[2 * i]     = __nv_bfloat162(h0, h1);
    ph[2 * i + 1] = __nv_bfloat162(h2, h3);
    pl[2 * i]     = __nv_bfloat162(l0, l1);
    pl[2 * i + 1] = __nv_bfloat162(l2, l3);
}

// ============================================================================
// time-shift mix -> bf16 hi/lo of xk, xv, xr
// ============================================================================
__global__ void mix_kernel(const float* __restrict__ hidden,
                           const float* __restrict__ tmk,
                           const float* __restrict__ tmv,
                           const float* __restrict__ tmr) {
    const int H4 = H_ / 4;
    int i = blockIdx.x * blockDim.x + threadIdx.x;   // float4 index
    int h4  = i % H4;
    int row = i / H4;
    int s   = row & (S_ - 1);

    float4 cur = ((const float4*)hidden)[i];
    float4 sh  = make_float4(0.f, 0.f, 0.f, 0.f);
    if (s != 0) sh = ((const float4*)hidden)[i - H4];

    float4 mk = ((const float4*)tmk)[h4];
    float4 mv = ((const float4*)tmv)[h4];
    float4 mr = ((const float4*)tmr)[h4];

    float dx = cur.x - sh.x, dy = cur.y - sh.y, dz = cur.z - sh.z, dw = cur.w - sh.w;

    float vals[3][4];
    vals[0][0] = fmaf(mk.x, dx, sh.x); vals[0][1] = fmaf(mk.y, dy, sh.y);
    vals[0][2] = fmaf(mk.z, dz, sh.z); vals[0][3] = fmaf(mk.w, dw, sh.w);
    vals[1][0] = fmaf(mv.x, dx, sh.x); vals[1][1] = fmaf(mv.y, dy, sh.y);
    vals[1][2] = fmaf(mv.z, dz, sh.z); vals[1][3] = fmaf(mv.w, dw, sh.w);
    vals[2][0] = fmaf(mr.x, dx, sh.x); vals[2][1] = fmaf(mr.y, dy, sh.y);
    vals[2][2] = fmaf(mr.z, dz, sh.z); vals[2][3] = fmaf(mr.w, dw, sh.w);

    __nv_bfloat162* dh[3] = {(__nv_bfloat162*)g_xkh, (__nv_bfloat162*)g_xvh, (__nv_bfloat162*)g_xrh};
    __nv_bfloat162* dl[3] = {(__nv_bfloat162*)g_xkl, (__nv_bfloat162*)g_xvl, (__nv_bfloat162*)g_xrl};
#pragma unroll
    for (int t = 0; t < 3; ++t) {
        __nv_bfloat16 h0, l0, h1, l1, h2, l2, h3, l3;
        split_bf(vals[t][0], h0, l0); split_bf(vals[t][1], h1, l1);
        split_bf(vals[t][2], h2, l2); split_bf(vals[t][3], h3, l3);
        dh[t][2 * i]     = __nv_bfloat162(h0, h1);
        dh[t][2 * i + 1] = __nv_bfloat162(h2, h3);
        dl[t][2 * i]     = __nv_bfloat162(l0, l1);
        dl[t][2 * i + 1] = __nv_bfloat162(l2, l3);
    }
}

// ============================================================================
// HMMA GEMM, bf16x3 split as virtual K' = 3*2048.
// CTA 128x128, 512 threads / 16 warps (4x4), warp tile 32x32 (m16n8k16).
// BK=64 per stage (128B rows, SW128), ldmatrix.x4, 3-stage cp.async pipeline.
// ============================================================================
#define NST 3
#define BKS 64
#define STGB (128 * 128)                // bytes per matrix per stage
#define NSTEP (3 * K_ / BKS)            // 96

__global__ __launch_bounds__(512) void gemm_hmma(int which, float* __restrict__ Cout) {
    extern __shared__ char sm[];

    const __nv_bfloat16 *Ah, *Al, *Bh, *Bl;
    float* C;
    bool sig = false;
    if (which == 0)      { Ah = g_xkh; Al = g_xkl; Bh = g_wh[0]; Bl = g_wl[0]; C = g_k; }
    else if (which == 1) { Ah = g_xvh; Al = g_xvl; Bh = g_wh[1]; Bl = g_wl[1]; C = g_v; }
    else if (which == 2) { Ah = g_xrh; Al = g_xrl; Bh = g_wh[2]; Bl = g_wl[2]; C = g_r; sig = true; }
    else                 { Ah = g_yh;  Al = g_yl;  Bh = g_wh[3]; Bl = g_wl[3]; C = Cout; }

    const int tid  = threadIdx.x;
    const int wid  = tid >> 5;
    const int lane = tid & 31;
    const int wm   = wid >> 2;      // 0..3 : 32-row strip
    const int wn   = wid & 3;       // 0..3 : 32-col strip
    const int g    = lane >> 2;     // 0..7
    const int t4   = lane & 3;      // 0..3

    const int rowA0 = blockIdx.y * 128;
    const int rowB0 = blockIdx.x * 128;

    const uint32_t sA0 = smem_u32(sm);
    const uint32_t sB0 = sA0 + NST * STGB;

    auto load_stage = [&](int st, int slot) {
        int phase = st >> 5;                 // 32 stages per split-phase
        int k0 = (st & 31) * BKS;
        const __nv_bfloat16* Ap = (phase < 2) ? Ah : Al;
        const __nv_bfloat16* Bp = (phase == 1) ? Bl : Bh;
#pragma unroll
        for (int i = 0; i < 2; ++i) {
            int id = i * 512 + tid;          // 0..1023
            int row = id >> 3, c = id & 7;
            uint32_t sw = swz(row * 128 + c * 16);
            cpasync16(sA0 + slot * STGB + sw, Ap + (size_t)(rowA0 + row) * K_ + k0 + c * 8);
        }
#pragma unroll
        for (int i = 0; i < 2; ++i) {
            int id = i * 512 + tid;
            int row = id >> 3, c = id & 7;
            uint32_t sw = swz(row * 128 + c * 16);
            cpasync16(sB0 + slot * STGB + sw, Bp + (size_t)(rowB0 + row) * K_ + k0 + c * 8);
        }
    };

    // ldmatrix per-lane bases (x4: four 8x8 tiles selected by lane>>3)
    const int tsel = lane >> 3;             // 0..3
    const int rin  = lane & 7;
    // A tiles [m0k0, m8k0, m0k8, m8k8]
    const int aRowBase = wm * 32 + (tsel & 1) * 8 + rin;
    const int aColBase = (tsel >> 1) * 16;
    // B tiles [n0k0, n0k8, n8k0, n8k8]
    const int bRowBase = wn * 32 + (tsel >> 1) * 8 + rin;
    const int bColBase = (tsel & 1) * 16;

    float acc[2][4][4];
#pragma unroll
    for (int i = 0; i < 2; ++i)
#pragma unroll
        for (int j = 0; j < 4; ++j)
#pragma unroll
            for (int r = 0; r < 4; ++r) acc[i][j][r] = 0.f;

    load_stage(0, 0); cp_commit();
    load_stage(1, 1); cp_commit();

    for (int kt = 0; kt < NSTEP; ++kt) {
        const int slot = kt % NST;
        if (kt + 1 < NSTEP) cp_wait<1>(); else cp_wait<0>();
        __syncthreads();

        if (kt + 2 < NSTEP) { load_stage(kt + 2, (kt + 2) % NST); cp_commit(); }

        const uint32_t aBase = sA0 + slot * STGB;
        const uint32_t bBase = sB0 + slot * STGB;

#pragma unroll
        for (int kc = 0; kc < 4; ++kc) {
            uint32_t afr[2][4];
#pragma unroll
            for (int mt = 0; mt < 2; ++mt)
                ldsm4(afr[mt], aBase + swz((aRowBase + mt * 16) * 128 + kc * 32 + aColBase));
            uint32_t bfr[2][4];
#pragma unroll
            for (int np = 0; np < 2; ++np)
                ldsm4(bfr[np], bBase + swz((bRowBase + np * 16) * 128 + kc * 32 + bColBase));
#pragma unroll
            for (int mt = 0; mt < 2; ++mt)
#pragma unroll
                for (int nt = 0; nt < 4; ++nt)
                    mma16816(acc[mt][nt], afr[mt], &bfr[nt >> 1][(nt & 1) * 2]);
        }
    }

    // epilogue
#pragma unroll
    for (int mt = 0; mt < 2; ++mt) {
        size_t row = (size_t)rowA0 + wm * 32 + mt * 16 + g;
#pragma unroll
        for (int nt = 0; nt < 4; ++nt) {
            int col = rowB0 + wn * 32 + nt * 8 + 2 * t4;
            float2 lo = make_float2(acc[mt][nt][0], acc[mt][nt][1]);
            float2 hi = make_float2(acc[mt][nt][2], acc[mt][nt][3]);
            if (sig) {
                lo.x = 1.f / (1.f + __expf(-lo.x)); lo.y = 1.f / (1.f + __expf(-lo.y));
                hi.x = 1.f / (1.f + __expf(-hi.x)); hi.y = 1.f / (1.f + __expf(-hi.y));
            }
            *(float2*)(C + row * N_ + col) = lo;
            *(float2*)(C + (row + 8) * N_ + col) = hi;
        }
    }
}

// ============================================================================
// WKV scan with 16-deep register prefetch pipeline. One thread per (b,d).
// Loads for iteration s+16 issued while computing iteration s.
// ============================================================================
#define WKV_P 16

__global__ __launch_bounds__(64) void wkv_kernel(const float* __restrict__ time_decay,
                                                 const float* __restrict__ time_first) {
    int t = blockIdx.x * blockDim.x + threadIdx.x;
    int b = t >> 11;
    int d = t & (H_ - 1);

    float w  = -__expf(time_decay[d]);
    float tf = time_first[d];

    float num = 0.f, den = 0.f, mx = -1e38f;
    const size_t base = (size_t)b * S_ * H_ + d;

    float kb[WKV_P], vb[WKV_P], rb[WKV_P];
#pragma unroll
    for (int i = 0; i < WKV_P; ++i) {
        size_t p = base + (size_t)i * H_;
        kb[i] = g_k[p]; vb[i] = g_v[p]; rb[i] = g_r[p];
    }

    for (int s0 = 0; s0 < S_; s0 += WKV_P) {
#pragma unroll
        for (int u = 0; u < WKV_P; ++u) {
            const int s = s0 + u;
            const size_t idx = base + (size_t)s * H_;

            float k = kb[u], v = vb[u], r = rb[u];
            // issue prefetch for s+P immediately (slot u is now free)
            if (s + WKV_P < S_) {
                size_t p = idx + (size_t)WKV_P * H_;
                kb[u] = g_k[p]; vb[u] = g_v[p]; rb[u] = g_r[p];
            }

            float ktf = k + tf;
            float mo  = fmaxf(mx, ktf);
            float e1  = __expf(mx - mo);
            float e2  = __expf(ktf - mo);
            float out = __fdividef(e1 * num + e2 * v, e1 * den + e2);
            float y = r * out;
            __nv_bfloat16 h, l;
            split_bf(y, h, l);
            g_yh[idx] = h;
            g_yl[idx] = l;

            float mw  = mx + w;
            float mn  = fmaxf(mw, k);
            float e1n = __expf(mw - mn);
            float e2n = __expf(k - mn);
            num = e1n * num + e2n * v;
            den = e1n * den + e2n;
            mx  = mn;
        }
    }
}

// ============================================================================
// Launch
// ============================================================================
extern "C" void kernel_launch(void* const* d_in, const int* in_sizes, int n_in,
                              void* d_out, int out_size) {
    const float* hidden     = (const float*)d_in[0];
    const float* time_decay = (const float*)d_in[1];
    const float* time_first = (const float*)d_in[2];
    const float* tmk        = (const float*)d_in[3];
    const float* tmv        = (const float*)d_in[4];
    const float* tmr        = (const float*)d_in[5];
    const float* Wk         = (const float*)d_in[6];
    const float* Wv         = (const float*)d_in[7];
    const float* Wr         = (const float*)d_in[8];
    const float* Wo         = (const float*)d_in[9];
    float* out              = (float*)d_out;

    const int shm = 2 * NST * STGB;   // 96 KB
    cudaFuncSetAttribute(gemm_hmma, cudaFuncAttributeMaxDynamicSharedMemorySize, shm);

    // 0) weight conversion to bf16 hi/lo (one launch)
    {
        dim3 g((N_ * K_ / 4) / 256, 4);
        convw_all<<<g, 256>>>(Wk, Wv, Wr, Wo);
    }

    // 1) time-shift mix (fp32 -> bf16 hi/lo)
    mix_kernel<<<(M_ * H_ / 4) / 256, 256>>>(hidden, tmk, tmv, tmr);

    // 2) projection GEMMs
    dim3 gg(N_ / 128, M_ / 128);   // (16, 64)
    gemm_hmma<<<gg, 512, shm>>>(0, nullptr);
    gemm_hmma<<<gg, 512, shm>>>(1, nullptr);
    gemm_hmma<<<gg, 512, shm>>>(2, nullptr);

    // 3) WKV scan (writes y hi/lo)
    wkv_kernel<<<(B_ * H_) / 64, 64>>>(time_decay, time_first);

    // 4) output GEMM
    gemm_hmma<<<gg, 512, shm>>>(3, out);
}

// round 7
// speedup vs baseline: 2.3669x; 1.2367x over previous
#include <cuda_runtime.h>
#include <cuda_bf16.h>
#include <cstdint>

// Shapes: B=4, S=2048, H=D=2048
#define B_ 4
#define S_ 2048
#define H_ 2048
#define M_ (B_ * S_)   // 8192
#define N_ H_
#define K_ H_

// ---------------- scratch (static device arrays, no allocation) -------------
__device__ __nv_bfloat16 g_xkh[(size_t)M_ * H_], g_xkl[(size_t)M_ * H_];
__device__ __nv_bfloat16 g_xvh[(size_t)M_ * H_], g_xvl[(size_t)M_ * H_];
__device__ __nv_bfloat16 g_xrh[(size_t)M_ * H_], g_xrl[(size_t)M_ * H_];
__device__ __nv_bfloat16 g_yh [(size_t)M_ * H_], g_yl [(size_t)M_ * H_];
__device__ __nv_bfloat16 g_wh[4][(size_t)N_ * K_];
__device__ __nv_bfloat16 g_wl[4][(size_t)N_ * K_];
__device__ float g_k[(size_t)M_ * H_];
__device__ float g_v[(size_t)M_ * H_];
__device__ float g_r[(size_t)M_ * H_];

// ---------------- helpers ----------------
__device__ __forceinline__ uint32_t smem_u32(const void* p) {
    uint32_t a;
    asm("{ .reg .u64 t; cvta.to.shared.u64 t, %1; cvt.u32.u64 %0, t; }"
        : "=r"(a) : "l"(p));
    return a;
}
__device__ __forceinline__ void cpasync16(uint32_t dst, const void* src) {
    asm volatile("cp.async.cg.shared.global [%0], [%1], 16;" :: "r"(dst), "l"(src));
}
__device__ __forceinline__ void cp_commit() {
    asm volatile("cp.async.commit_group;" ::: "memory");
}
template <int N> __device__ __forceinline__ void cp_wait() {
    asm volatile("cp.async.wait_group %0;" :: "n"(N) : "memory");
}
__device__ __forceinline__ void ldsm4(uint32_t* r, uint32_t a) {
    asm volatile("ldmatrix.sync.aligned.m8n8.x4.shared.b16 {%0,%1,%2,%3}, [%4];"
                 : "=r"(r[0]), "=r"(r[1]), "=r"(r[2]), "=r"(r[3]) : "r"(a));
}
__device__ __forceinline__ void mma16816(float* c, const uint32_t* a, const uint32_t* b) {
    asm volatile(
        "mma.sync.aligned.m16n8k16.row.col.f32.bf16.bf16.f32 "
        "{%0,%1,%2,%3}, {%4,%5,%6,%7}, {%8,%9}, {%0,%1,%2,%3};"
        : "+f"(c[0]), "+f"(c[1]), "+f"(c[2]), "+f"(c[3])
        : "r"(a[0]), "r"(a[1]), "r"(a[2]), "r"(a[3]), "r"(b[0]), "r"(b[1]));
}
__device__ __forceinline__ void split_bf(float x, __nv_bfloat16& h, __nv_bfloat16& l) {
    h = __float2bfloat16(x);
    l = __float2bfloat16(x - __bfloat162float(h));
}
__device__ __forceinline__ uint32_t swz(uint32_t off) {   // SW128
    return off ^ ((off >> 3) & 0x70);
}

// ============================================================================
// Convert all four W matrices (fp32) to bf16 hi/lo. grid (4096, 4).
// ============================================================================
__global__ void convw_all(const float* __restrict__ W0, const float* __restrict__ W1,
                          const float* __restrict__ W2, const float* __restrict__ W3) {
    const int widx = blockIdx.y;
    const float* W = (widx == 0) ? W0 : (widx == 1) ? W1 : (widx == 2) ? W2 : W3;
    int i = blockIdx.x * blockDim.x + threadIdx.x;   // float4 index
    float4 w = ((const float4*)W)[i];
    __nv_bfloat16 h0, l0, h1, l1, h2, l2, h3, l3;
    split_bf(w.x, h0, l0); split_bf(w.y, h1, l1);
    split_bf(w.z, h2, l2); split_bf(w.w, h3, l3);
    __nv_bfloat162* ph = (__nv_bfloat162*)g_wh[widx];
    __nv_bfloat162* pl = (__nv_bfloat162*)g_wl[widx];
    ph[2 * i]     = __nv_bfloat162(h0, h1);
    ph[2 * i + 1] = __nv_bfloat162(h2, h3);
    pl[2 * i]     = __nv_bfloat162(l0, l1);
    pl[2 * i + 1] = __nv_bfloat162(l2, l3);
}

// ============================================================================
// time-shift mix -> bf16 hi/lo of xk, xv, xr
// ============================================================================
__global__ void mix_kernel(const float* __restrict__ hidden,
                           const float* __restrict__ tmk,
                           const float* __restrict__ tmv,
                           const float* __restrict__ tmr) {
    const int H4 = H_ / 4;
    int i = blockIdx.x * blockDim.x + threadIdx.x;   // float4 index
    int h4  = i % H4;
    int row = i / H4;
    int s   = row & (S_ - 1);

    float4 cur = ((const float4*)hidden)[i];
    float4 sh  = make_float4(0.f, 0.f, 0.f, 0.f);
    if (s != 0) sh = ((const float4*)hidden)[i - H4];

    float4 mk = ((const float4*)tmk)[h4];
    float4 mv = ((const float4*)tmv)[h4];
    float4 mr = ((const float4*)tmr)[h4];

    float dx = cur.x - sh.x, dy = cur.y - sh.y, dz = cur.z - sh.z, dw = cur.w - sh.w;

    float vals[3][4];
    vals[0][0] = fmaf(mk.x, dx, sh.x); vals[0][1] = fmaf(mk.y, dy, sh.y);
    vals[0][2] = fmaf(mk.z, dz, sh.z); vals[0][3] = fmaf(mk.w, dw, sh.w);
    vals[1][0] = fmaf(mv.x, dx, sh.x); vals[1][1] = fmaf(mv.y, dy, sh.y);
    vals[1][2] = fmaf(mv.z, dz, sh.z); vals[1][3] = fmaf(mv.w, dw, sh.w);
    vals[2][0] = fmaf(mr.x, dx, sh.x); vals[2][1] = fmaf(mr.y, dy, sh.y);
    vals[2][2] = fmaf(mr.z, dz, sh.z); vals[2][3] = fmaf(mr.w, dw, sh.w);

    __nv_bfloat162* dh[3] = {(__nv_bfloat162*)g_xkh, (__nv_bfloat162*)g_xvh, (__nv_bfloat162*)g_xrh};
    __nv_bfloat162* dl[3] = {(__nv_bfloat162*)g_xkl, (__nv_bfloat162*)g_xvl, (__nv_bfloat162*)g_xrl};
#pragma unroll
    for (int t = 0; t < 3; ++t) {
        __nv_bfloat16 h0, l0, h1, l1, h2, l2, h3, l3;
        split_bf(vals[t][0], h0, l0); split_bf(vals[t][1], h1, l1);
        split_bf(vals[t][2], h2, l2); split_bf(vals[t][3], h3, l3);
        dh[t][2 * i]     = __nv_bfloat162(h0, h1);
        dh[t][2 * i + 1] = __nv_bfloat162(h2, h3);
        dl[t][2 * i]     = __nv_bfloat162(l0, l1);
        dl[t][2 * i + 1] = __nv_bfloat162(l2, l3);
    }
}

// ============================================================================
// HMMA GEMM core, bf16x3 split as virtual K' = 3*2048.
// CTA 128x128, 512 threads / 16 warps (4x4), warp tile 32x32.
// BK=64 per stage (SW128), ldmatrix.x4, 3-stage cp.async pipeline.
// __launch_bounds__(512, 2): <=64 regs -> 2 CTAs/SM (192KB smem total).
// ============================================================================
#define NST 3
#define BKS 64
#define STGB (128 * 128)                // bytes per matrix per stage
#define NSTEP (3 * K_ / BKS)            // 96

__device__ __forceinline__ void gemm_core(
    const __nv_bfloat16* __restrict__ Ah, const __nv_bfloat16* __restrict__ Al,
    const __nv_bfloat16* __restrict__ Bh, const __nv_bfloat16* __restrict__ Bl,
    float* __restrict__ C, bool sig, char* sm, int bx, int by) {

    const int tid  = threadIdx.x;
    const int wid  = tid >> 5;
    const int lane = tid & 31;
    const int wm   = wid >> 2;      // 0..3
    const int wn   = wid & 3;       // 0..3
    const int g    = lane >> 2;
    const int t4   = lane & 3;

    const int rowA0 = by * 128;
    const int rowB0 = bx * 128;

    const uint32_t sA0 = smem_u32(sm);
    const uint32_t sB0 = sA0 + NST * STGB;

    auto load_stage = [&](int st, int slot) {
        int phase = st >> 5;
        int k0 = (st & 31) * BKS;
        const __nv_bfloat16* Ap = (phase < 2) ? Ah : Al;
        const __nv_bfloat16* Bp = (phase == 1) ? Bl : Bh;
#pragma unroll
        for (int i = 0; i < 2; ++i) {
            int id = i * 512 + tid;
            int row = id >> 3, c = id & 7;
            uint32_t sw = swz(row * 128 + c * 16);
            cpasync16(sA0 + slot * STGB + sw, Ap + (size_t)(rowA0 + row) * K_ + k0 + c * 8);
        }
#pragma unroll
        for (int i = 0; i < 2; ++i) {
            int id = i * 512 + tid;
            int row = id >> 3, c = id & 7;
            uint32_t sw = swz(row * 128 + c * 16);
            cpasync16(sB0 + slot * STGB + sw, Bp + (size_t)(rowB0 + row) * K_ + k0 + c * 8);
        }
    };

    const int tsel = lane >> 3;
    const int rin  = lane & 7;
    const int aRowBase = wm * 32 + (tsel & 1) * 8 + rin;
    const int aColBase = (tsel >> 1) * 16;
    const int bRowBase = wn * 32 + (tsel >> 1) * 8 + rin;
    const int bColBase = (tsel & 1) * 16;

    float acc[2][4][4];
#pragma unroll
    for (int i = 0; i < 2; ++i)
#pragma unroll
        for (int j = 0; j < 4; ++j)
#pragma unroll
            for (int r = 0; r < 4; ++r) acc[i][j][r] = 0.f;

    load_stage(0, 0); cp_commit();
    load_stage(1, 1); cp_commit();

    for (int kt = 0; kt < NSTEP; ++kt) {
        const int slot = kt % NST;
        if (kt + 1 < NSTEP) cp_wait<1>(); else cp_wait<0>();
        __syncthreads();

        if (kt + 2 < NSTEP) { load_stage(kt + 2, (kt + 2) % NST); cp_commit(); }

        const uint32_t aBase = sA0 + slot * STGB;
        const uint32_t bBase = sB0 + slot * STGB;

#pragma unroll
        for (int kc = 0; kc < 4; ++kc) {
            uint32_t afr[2][4];
#pragma unroll
            for (int mt = 0; mt < 2; ++mt)
                ldsm4(afr[mt], aBase + swz((aRowBase + mt * 16) * 128 + kc * 32 + aColBase));
            uint32_t bfr[2][4];
#pragma unroll
            for (int np = 0; np < 2; ++np)
                ldsm4(bfr[np], bBase + swz((bRowBase + np * 16) * 128 + kc * 32 + bColBase));
#pragma unroll
            for (int mt = 0; mt < 2; ++mt)
#pragma unroll
                for (int nt = 0; nt < 4; ++nt)
                    mma16816(acc[mt][nt], afr[mt], &bfr[nt >> 1][(nt & 1) * 2]);
        }
    }

    // epilogue
#pragma unroll
    for (int mt = 0; mt < 2; ++mt) {
        size_t row = (size_t)rowA0 + wm * 32 + mt * 16 + g;
#pragma unroll
        for (int nt = 0; nt < 4; ++nt) {
            int col = rowB0 + wn * 32 + nt * 8 + 2 * t4;
            float2 lo = make_float2(acc[mt][nt][0], acc[mt][nt][1]);
            float2 hi = make_float2(acc[mt][nt][2], acc[mt][nt][3]);
            if (sig) {
                lo.x = 1.f / (1.f + __expf(-lo.x)); lo.y = 1.f / (1.f + __expf(-lo.y));
                hi.x = 1.f / (1.f + __expf(-hi.x)); hi.y = 1.f / (1.f + __expf(-hi.y));
            }
            *(float2*)(C + row * N_ + col) = lo;
            *(float2*)(C + (row + 8) * N_ + col) = hi;
        }
    }
}

// Fused projection GEMMs: blockIdx.z selects k/v/r
__global__ __launch_bounds__(512, 2) void gemm_proj() {
    extern __shared__ char sm[];
    const int z = blockIdx.z;
    if (z == 0)
        gemm_core(g_xkh, g_xkl, g_wh[0], g_wl[0], g_k, false, sm, blockIdx.x, blockIdx.y);
    else if (z == 1)
        gemm_core(g_xvh, g_xvl, g_wh[1], g_wl[1], g_v, false, sm, blockIdx.x, blockIdx.y);
    else
        gemm_core(g_xrh, g_xrl, g_wh[2], g_wl[2], g_r, true, sm, blockIdx.x, blockIdx.y);
}

// Output GEMM
__global__ __launch_bounds__(512, 2) void gemm_out(float* __restrict__ out) {
    extern __shared__ char sm[];
    gemm_core(g_yh, g_yl, g_wh[3], g_wl[3], out, false, sm, blockIdx.x, blockIdx.y);
}

// ============================================================================
// WKV scan with 16-deep register prefetch pipeline. One thread per (b,d).
// ============================================================================
#define WKV_P 16

__global__ __launch_bounds__(32) void wkv_kernel(const float* __restrict__ time_decay,
                                                 const float* __restrict__ time_first) {
    int t = blockIdx.x * blockDim.x + threadIdx.x;
    int b = t >> 11;
    int d = t & (H_ - 1);

    float w  = -__expf(time_decay[d]);
    float tf = time_first[d];

    float num = 0.f, den = 0.f, mx = -1e38f;
    const size_t base = (size_t)b * S_ * H_ + d;

    float kb[WKV_P], vb[WKV_P], rb[WKV_P];
#pragma unroll
    for (int i = 0; i < WKV_P; ++i) {
        size_t p = base + (size_t)i * H_;
        kb[i] = g_k[p]; vb[i] = g_v[p]; rb[i] = g_r[p];
    }

    for (int s0 = 0; s0 < S_; s0 += WKV_P) {
#pragma unroll
        for (int u = 0; u < WKV_P; ++u) {
            const int s = s0 + u;
            const size_t idx = base + (size_t)s * H_;

            float k = kb[u], v = vb[u], r = rb[u];
            if (s + WKV_P < S_) {
                size_t p = idx + (size_t)WKV_P * H_;
                kb[u] = g_k[p]; vb[u] = g_v[p]; rb[u] = g_r[p];
            }

            float ktf = k + tf;
            float mo  = fmaxf(mx, ktf);
            float e1  = __expf(mx - mo);
            float e2  = __expf(ktf - mo);
            float out = __fdividef(e1 * num + e2 * v, e1 * den + e2);
            float y = r * out;
            __nv_bfloat16 h, l;
            split_bf(y, h, l);
            g_yh[idx] = h;
            g_yl[idx] = l;

            float mw  = mx + w;
            float mn  = fmaxf(mw, k);
            float e1n = __expf(mw - mn);
            float e2n = __expf(k - mn);
            num = e1n * num + e2n * v;
            den = e1n * den + e2n;
            mx  = mn;
        }
    }
}

// ============================================================================
// Launch
// ============================================================================
extern "C" void kernel_launch(void* const* d_in, const int* in_sizes, int n_in,
                              void* d_out, int out_size) {
    const float* hidden     = (const float*)d_in[0];
    const float* time_decay = (const float*)d_in[1];
    const float* time_first = (const float*)d_in[2];
    const float* tmk        = (const float*)d_in[3];
    const float* tmv        = (const float*)d_in[4];
    const float* tmr        = (const float*)d_in[5];
    const float* Wk         = (const float*)d_in[6];
    const float* Wv         = (const float*)d_in[7];
    const float* Wr         = (const float*)d_in[8];
    const float* Wo         = (const float*)d_in[9];
    float* out              = (float*)d_out;

    const int shm = 2 * NST * STGB;   // 96 KB
    cudaFuncSetAttribute(gemm_proj, cudaFuncAttributeMaxDynamicSharedMemorySize, shm);
    cudaFuncSetAttribute(gemm_out,  cudaFuncAttributeMaxDynamicSharedMemorySize, shm);

    // 0) weight conversion to bf16 hi/lo
    {
        dim3 g((N_ * K_ / 4) / 256, 4);
        convw_all<<<g, 256>>>(Wk, Wv, Wr, Wo);
    }

    // 1) time-shift mix (fp32 -> bf16 hi/lo)
    mix_kernel<<<(M_ * H_ / 4) / 256, 256>>>(hidden, tmk, tmv, tmr);

    // 2) fused projection GEMMs (k, v, r)
    dim3 gg(N_ / 128, M_ / 128, 3);   // (16, 64, 3)
    gemm_proj<<<gg, 512, shm>>>();

    // 3) WKV scan (writes y hi/lo)
    wkv_kernel<<<(B_ * H_) / 32, 32>>>(time_decay, time_first);

    // 4) output GEMM
    dim3 go(N_ / 128, M_ / 128);
    gemm_out<<<go, 512, shm>>>(out);
}

// round 8
// speedup vs baseline: 3.3341x; 1.4086x over previous
#include <cuda_runtime.h>
#include <cuda_bf16.h>
#include <cuda_fp16.h>
#include <cstdint>

// Shapes: B=4, S=2048, H=D=2048
#define B_ 4
#define S_ 2048
#define H_ 2048
#define M_ (B_ * S_)   // 8192
#define N_ H_
#define K_ H_

// ---------------- scratch (static device arrays, no allocation) -------------
// fp16 split: A = Ah + Al (exact to ~22 bits); W rounded once to fp16.
__device__ __half g_xkh[(size_t)M_ * H_], g_xkl[(size_t)M_ * H_];
__device__ __half g_xvh[(size_t)M_ * H_], g_xvl[(size_t)M_ * H_];
__device__ __half g_xrh[(size_t)M_ * H_], g_xrl[(size_t)M_ * H_];
__device__ __half g_yh [(size_t)M_ * H_], g_yl [(size_t)M_ * H_];
__device__ __half g_wf[4][(size_t)N_ * K_];
__device__ float g_k[(size_t)M_ * H_];
__device__ float g_v[(size_t)M_ * H_];
__device__ float g_r[(size_t)M_ * H_];

// ---------------- helpers ----------------
__device__ __forceinline__ uint32_t smem_u32(const void* p) {
    uint32_t a;
    asm("{ .reg .u64 t; cvta.to.shared.u64 t, %1; cvt.u32.u64 %0, t; }"
        : "=r"(a) : "l"(p));
    return a;
}
__device__ __forceinline__ void cpasync16(uint32_t dst, const void* src) {
    asm volatile("cp.async.cg.shared.global [%0], [%1], 16;" :: "r"(dst), "l"(src));
}
__device__ __forceinline__ void cp_commit() {
    asm volatile("cp.async.commit_group;" ::: "memory");
}
template <int N> __device__ __forceinline__ void cp_wait() {
    asm volatile("cp.async.wait_group %0;" :: "n"(N) : "memory");
}
__device__ __forceinline__ void ldsm4(uint32_t* r, uint32_t a) {
    asm volatile("ldmatrix.sync.aligned.m8n8.x4.shared.b16 {%0,%1,%2,%3}, [%4];"
                 : "=r"(r[0]), "=r"(r[1]), "=r"(r[2]), "=r"(r[3]) : "r"(a));
}
__device__ __forceinline__ void mma16816(float* c, const uint32_t* a, const uint32_t* b) {
    asm volatile(
        "mma.sync.aligned.m16n8k16.row.col.f32.f16.f16.f32 "
        "{%0,%1,%2,%3}, {%4,%5,%6,%7}, {%8,%9}, {%0,%1,%2,%3};"
        : "+f"(c[0]), "+f"(c[1]), "+f"(c[2]), "+f"(c[3])
        : "r"(a[0]), "r"(a[1]), "r"(a[2]), "r"(a[3]), "r"(b[0]), "r"(b[1]));
}
__device__ __forceinline__ void split_h(float x, __half& h, __half& l) {
    h = __float2half_rn(x);
    l = __float2half_rn(x - __half2float(h));
}
__device__ __forceinline__ uint32_t swz(uint32_t off) {   // SW128
    return off ^ ((off >> 3) & 0x70);
}

// ============================================================================
// Convert all four W matrices (fp32) to fp16. grid (4096, 4).
// ============================================================================
__global__ void convw_all(const float* __restrict__ W0, const float* __restrict__ W1,
                          const float* __restrict__ W2, const float* __restrict__ W3) {
    const int widx = blockIdx.y;
    const float* W = (widx == 0) ? W0 : (widx == 1) ? W1 : (widx == 2) ? W2 : W3;
    int i = blockIdx.x * blockDim.x + threadIdx.x;   // float4 index
    float4 w = ((const float4*)W)[i];
    __half2* pf = (__half2*)g_wf[widx];
    pf[2 * i]     = __half2(__float2half_rn(w.x), __float2half_rn(w.y));
    pf[2 * i + 1] = __half2(__float2half_rn(w.z), __float2half_rn(w.w));
}

// ============================================================================
// time-shift mix -> fp16 hi/lo of xk, xv, xr
// ============================================================================
__global__ void mix_kernel(const float* __restrict__ hidden,
                           const float* __restrict__ tmk,
                           const float* __restrict__ tmv,
                           const float* __restrict__ tmr) {
    const int H4 = H_ / 4;
    int i = blockIdx.x * blockDim.x + threadIdx.x;   // float4 index
    int h4  = i % H4;
    int row = i / H4;
    int s   = row & (S_ - 1);

    float4 cur = ((const float4*)hidden)[i];
    float4 sh  = make_float4(0.f, 0.f, 0.f, 0.f);
    if (s != 0) sh = ((const float4*)hidden)[i - H4];

    float4 mk = ((const float4*)tmk)[h4];
    float4 mv = ((const float4*)tmv)[h4];
    float4 mr = ((const float4*)tmr)[h4];

    float dx = cur.x - sh.x, dy = cur.y - sh.y, dz = cur.z - sh.z, dw = cur.w - sh.w;

    float vals[3][4];
    vals[0][0] = fmaf(mk.x, dx, sh.x); vals[0][1] = fmaf(mk.y, dy, sh.y);
    vals[0][2] = fmaf(mk.z, dz, sh.z); vals[0][3] = fmaf(mk.w, dw, sh.w);
    vals[1][0] = fmaf(mv.x, dx, sh.x); vals[1][1] = fmaf(mv.y, dy, sh.y);
    vals[1][2] = fmaf(mv.z, dz, sh.z); vals[1][3] = fmaf(mv.w, dw, sh.w);
    vals[2][0] = fmaf(mr.x, dx, sh.x); vals[2][1] = fmaf(mr.y, dy, sh.y);
    vals[2][2] = fmaf(mr.z, dz, sh.z); vals[2][3] = fmaf(mr.w, dw, sh.w);

    __half2* dh[3] = {(__half2*)g_xkh, (__half2*)g_xvh, (__half2*)g_xrh};
    __half2* dl[3] = {(__half2*)g_xkl, (__half2*)g_xvl, (__half2*)g_xrl};
#pragma unroll
    for (int t = 0; t < 3; ++t) {
        __half h0, l0, h1, l1, h2, l2, h3, l3;
        split_h(vals[t][0], h0, l0); split_h(vals[t][1], h1, l1);
        split_h(vals[t][2], h2, l2); split_h(vals[t][3], h3, l3);
        dh[t][2 * i]     = __half2(h0, h1);
        dh[t][2 * i + 1] = __half2(h2, h3);
        dl[t][2 * i]     = __half2(l0, l1);
        dl[t][2 * i + 1] = __half2(l2, l3);
    }
}

// ============================================================================
// HMMA GEMM core, fp16 A-split as virtual K' = 2*2048.
// CTA 128x128, 512 threads / 16 warps (4x4), warp tile 32x32.
// BK=64 per stage (SW128), ldmatrix.x4, 3-stage cp.async pipeline.
// __launch_bounds__(512, 2): <=64 regs -> 2 CTAs/SM.
// ============================================================================
#define NST 3
#define BKS 64
#define STGB (128 * 128)                // bytes per matrix per stage
#define NSTEP (2 * K_ / BKS)            // 64

__device__ __forceinline__ void gemm_core(
    const __half* __restrict__ Ah, const __half* __restrict__ Al,
    const __half* __restrict__ Bf,
    float* __restrict__ C, bool sig, char* sm, int bx, int by) {

    const int tid  = threadIdx.x;
    const int wid  = tid >> 5;
    const int lane = tid & 31;
    const int wm   = wid >> 2;      // 0..3
    const int wn   = wid & 3;       // 0..3
    const int g    = lane >> 2;
    const int t4   = lane & 3;

    const int rowA0 = by * 128;
    const int rowB0 = bx * 128;

    const uint32_t sA0 = smem_u32(sm);
    const uint32_t sB0 = sA0 + NST * STGB;

    auto load_stage = [&](int st, int slot) {
        int phase = st >> 5;                 // 0: Ah, 1: Al (B same)
        int k0 = (st & 31) * BKS;
        const __half* Ap = phase ? Al : Ah;
#pragma unroll
        for (int i = 0; i < 2; ++i) {
            int id = i * 512 + tid;
            int row = id >> 3, c = id & 7;
            uint32_t sw = swz(row * 128 + c * 16);
            cpasync16(sA0 + slot * STGB + sw, Ap + (size_t)(rowA0 + row) * K_ + k0 + c * 8);
        }
#pragma unroll
        for (int i = 0; i < 2; ++i) {
            int id = i * 512 + tid;
            int row = id >> 3, c = id & 7;
            uint32_t sw = swz(row * 128 + c * 16);
            cpasync16(sB0 + slot * STGB + sw, Bf + (size_t)(rowB0 + row) * K_ + k0 + c * 8);
        }
    };

    const int tsel = lane >> 3;
    const int rin  = lane & 7;
    const int aRowBase = wm * 32 + (tsel & 1) * 8 + rin;
    const int aColBase = (tsel >> 1) * 16;
    const int bRowBase = wn * 32 + (tsel >> 1) * 8 + rin;
    const int bColBase = (tsel & 1) * 16;

    float acc[2][4][4];
#pragma unroll
    for (int i = 0; i < 2; ++i)
#pragma unroll
        for (int j = 0; j < 4; ++j)
#pragma unroll
            for (int r = 0; r < 4; ++r) acc[i][j][r] = 0.f;

    load_stage(0, 0); cp_commit();
    load_stage(1, 1); cp_commit();

    for (int kt = 0; kt < NSTEP; ++kt) {
        const int slot = kt % NST;
        if (kt + 1 < NSTEP) cp_wait<1>(); else cp_wait<0>();
        __syncthreads();

        if (kt + 2 < NSTEP) { load_stage(kt + 2, (kt + 2) % NST); cp_commit(); }

        const uint32_t aBase = sA0 + slot * STGB;
        const uint32_t bBase = sB0 + slot * STGB;

#pragma unroll
        for (int kc = 0; kc < 4; ++kc) {
            uint32_t afr[2][4];
#pragma unroll
            for (int mt = 0; mt < 2; ++mt)
                ldsm4(afr[mt], aBase + swz((aRowBase + mt * 16) * 128 + kc * 32 + aColBase));
            uint32_t bfr[2][4];
#pragma unroll
            for (int np = 0; np < 2; ++np)
                ldsm4(bfr[np], bBase + swz((bRowBase + np * 16) * 128 + kc * 32 + bColBase));
#pragma unroll
            for (int mt = 0; mt < 2; ++mt)
#pragma unroll
                for (int nt = 0; nt < 4; ++nt)
                    mma16816(acc[mt][nt], afr[mt], &bfr[nt >> 1][(nt & 1) * 2]);
        }
    }

    // epilogue
#pragma unroll
    for (int mt = 0; mt < 2; ++mt) {
        size_t row = (size_t)rowA0 + wm * 32 + mt * 16 + g;
#pragma unroll
        for (int nt = 0; nt < 4; ++nt) {
            int col = rowB0 + wn * 32 + nt * 8 + 2 * t4;
            float2 lo = make_float2(acc[mt][nt][0], acc[mt][nt][1]);
            float2 hi = make_float2(acc[mt][nt][2], acc[mt][nt][3]);
            if (sig) {
                lo.x = 1.f / (1.f + __expf(-lo.x)); lo.y = 1.f / (1.f + __expf(-lo.y));
                hi.x = 1.f / (1.f + __expf(-hi.x)); hi.y = 1.f / (1.f + __expf(-hi.y));
            }
            *(float2*)(C + row * N_ + col) = lo;
            *(float2*)(C + (row + 8) * N_ + col) = hi;
        }
    }
}

// Fused projection GEMMs: blockIdx.z selects k/v/r
__global__ __launch_bounds__(512, 2) void gemm_proj() {
    extern __shared__ char sm[];
    const int z = blockIdx.z;
    if (z == 0)
        gemm_core(g_xkh, g_xkl, g_wf[0], g_k, false, sm, blockIdx.x, blockIdx.y);
    else if (z == 1)
        gemm_core(g_xvh, g_xvl, g_wf[1], g_v, false, sm, blockIdx.x, blockIdx.y);
    else
        gemm_core(g_xrh, g_xrl, g_wf[2], g_r, true, sm, blockIdx.x, blockIdx.y);
}

// Output GEMM
__global__ __launch_bounds__(512, 2) void gemm_out(float* __restrict__ out) {
    extern __shared__ char sm[];
    gemm_core(g_yh, g_yl, g_wf[3], out, false, sm, blockIdx.x, blockIdx.y);
}

// ============================================================================
// WKV scan with 16-deep register prefetch pipeline. One thread per (b,d).
// ============================================================================
#define WKV_P 16

__global__ __launch_bounds__(32) void wkv_kernel(const float* __restrict__ time_decay,
                                                 const float* __restrict__ time_first) {
    int t = blockIdx.x * blockDim.x + threadIdx.x;
    int b = t >> 11;
    int d = t & (H_ - 1);

    float w  = -__expf(time_decay[d]);
    float tf = time_first[d];

    float num = 0.f, den = 0.f, mx = -1e38f;
    const size_t base = (size_t)b * S_ * H_ + d;

    float kb[WKV_P], vb[WKV_P], rb[WKV_P];
#pragma unroll
    for (int i = 0; i < WKV_P; ++i) {
        size_t p = base + (size_t)i * H_;
        kb[i] = g_k[p]; vb[i] = g_v[p]; rb[i] = g_r[p];
    }

    for (int s0 = 0; s0 < S_; s0 += WKV_P) {
#pragma unroll
        for (int u = 0; u < WKV_P; ++u) {
            const int s = s0 + u;
            const size_t idx = base + (size_t)s * H_;

            float k = kb[u], v = vb[u], r = rb[u];
            if (s + WKV_P < S_) {
                size_t p = idx + (size_t)WKV_P * H_;
                kb[u] = g_k[p]; vb[u] = g_v[p]; rb[u] = g_r[p];
            }

            float ktf = k + tf;
            float mo  = fmaxf(mx, ktf);
            float e1  = __expf(mx - mo);
            float e2  = __expf(ktf - mo);
            float out = __fdividef(e1 * num + e2 * v, e1 * den + e2);
            float y = r * out;
            __half h, l;
            split_h(y, h, l);
            g_yh[idx] = h;
            g_yl[idx] = l;

            float mw  = mx + w;
            float mn  = fmaxf(mw, k);
            float e1n = __expf(mw - mn);
            float e2n = __expf(k - mn);
            num = e1n * num + e2n * v;
            den = e1n * den + e2n;
            mx  = mn;
        }
    }
}

// ============================================================================
// Launch
// ============================================================================
extern "C" void kernel_launch(void* const* d_in, const int* in_sizes, int n_in,
                              void* d_out, int out_size) {
    const float* hidden     = (const float*)d_in[0];
    const float* time_decay = (const float*)d_in[1];
    const float* time_first = (const float*)d_in[2];
    const float* tmk        = (const float*)d_in[3];
    const float* tmv        = (const float*)d_in[4];
    const float* tmr        = (const float*)d_in[5];
    const float* Wk         = (const float*)d_in[6];
    const float* Wv         = (const float*)d_in[7];
    const float* Wr         = (const float*)d_in[8];
    const float* Wo         = (const float*)d_in[9];
    float* out              = (float*)d_out;

    const int shm = 2 * NST * STGB;   // 96 KB
    cudaFuncSetAttribute(gemm_proj, cudaFuncAttributeMaxDynamicSharedMemorySize, shm);
    cudaFuncSetAttribute(gemm_out,  cudaFuncAttributeMaxDynamicSharedMemorySize, shm);

    // 0) weight conversion to fp16
    {
        dim3 g((N_ * K_ / 4) / 256, 4);
        convw_all<<<g, 256>>>(Wk, Wv, Wr, Wo);
    }

    // 1) time-shift mix (fp32 -> fp16 hi/lo)
    mix_kernel<<<(M_ * H_ / 4) / 256, 256>>>(hidden, tmk, tmv, tmr);

    // 2) fused projection GEMMs (k, v, r)
    dim3 gg(N_ / 128, M_ / 128, 3);   // (16, 64, 3)
    gemm_proj<<<gg, 512, shm>>>();

    // 3) WKV scan (writes y hi/lo)
    wkv_kernel<<<(B_ * H_) / 32, 32>>>(time_decay, time_first);

    // 4) output GEMM
    dim3 go(N_ / 128, M_ / 128);
    gemm_out<<<go, 512, shm>>>(out);
}

// round 9
// speedup vs baseline: 4.9087x; 1.4722x over previous
#include <cuda_runtime.h>
#include <cuda_fp16.h>
#include <cstdint>

// Shapes: B=4, S=2048, H=D=2048
#define B_ 4
#define S_ 2048
#define H_ 2048
#define M_ (B_ * S_)   // 8192
#define N_ H_
#define K_ H_

// ---------------- scratch (static device arrays, no allocation) -------------
__device__ __half g_xk[(size_t)M_ * H_];
__device__ __half g_xv[(size_t)M_ * H_];
__device__ __half g_xr[(size_t)M_ * H_];
__device__ __half g_y [(size_t)M_ * H_];
__device__ __half g_wf[4][(size_t)N_ * K_];
__device__ float g_k[(size_t)M_ * H_];
__device__ float g_v[(size_t)M_ * H_];
__device__ float g_r[(size_t)M_ * H_];

// ---------------- helpers ----------------
__device__ __forceinline__ uint32_t smem_u32(const void* p) {
    uint32_t a;
    asm("{ .reg .u64 t; cvta.to.shared.u64 t, %1; cvt.u32.u64 %0, t; }"
        : "=r"(a) : "l"(p));
    return a;
}
__device__ __forceinline__ void cpasync16(uint32_t dst, const void* src) {
    asm volatile("cp.async.cg.shared.global [%0], [%1], 16;" :: "r"(dst), "l"(src));
}
__device__ __forceinline__ void cp_commit() {
    asm volatile("cp.async.commit_group;" ::: "memory");
}
template <int N> __device__ __forceinline__ void cp_wait() {
    asm volatile("cp.async.wait_group %0;" :: "n"(N) : "memory");
}
__device__ __forceinline__ void ldsm4(uint32_t* r, uint32_t a) {
    asm volatile("ldmatrix.sync.aligned.m8n8.x4.shared.b16 {%0,%1,%2,%3}, [%4];"
                 : "=r"(r[0]), "=r"(r[1]), "=r"(r[2]), "=r"(r[3]) : "r"(a));
}
__device__ __forceinline__ void mma16816(float* c, const uint32_t* a, const uint32_t* b) {
    asm volatile(
        "mma.sync.aligned.m16n8k16.row.col.f32.f16.f16.f32 "
        "{%0,%1,%2,%3}, {%4,%5,%6,%7}, {%8,%9}, {%0,%1,%2,%3};"
        : "+f"(c[0]), "+f"(c[1]), "+f"(c[2]), "+f"(c[3])
        : "r"(a[0]), "r"(a[1]), "r"(a[2]), "r"(a[3]), "r"(b[0]), "r"(b[1]));
}
__device__ __forceinline__ uint32_t swz(uint32_t off) {   // SW128
    return off ^ ((off >> 3) & 0x70);
}

// ============================================================================
// Convert all four W matrices (fp32) to fp16. grid (4096, 4).
// ============================================================================
__global__ void convw_all(const float* __restrict__ W0, const float* __restrict__ W1,
                          const float* __restrict__ W2, const float* __restrict__ W3) {
    const int widx = blockIdx.y;
    const float* W = (widx == 0) ? W0 : (widx == 1) ? W1 : (widx == 2) ? W2 : W3;
    int i = blockIdx.x * blockDim.x + threadIdx.x;   // float4 index
    float4 w = ((const float4*)W)[i];
    __half2* pf = (__half2*)g_wf[widx];
    pf[2 * i]     = __half2(__float2half_rn(w.x), __float2half_rn(w.y));
    pf[2 * i + 1] = __half2(__float2half_rn(w.z), __float2half_rn(w.w));
}

// ============================================================================
// time-shift mix -> fp16 xk, xv, xr
// ============================================================================
__global__ void mix_kernel(const float* __restrict__ hidden,
                           const float* __restrict__ tmk,
                           const float* __restrict__ tmv,
                           const float* __restrict__ tmr) {
    const int H4 = H_ / 4;
    int i = blockIdx.x * blockDim.x + threadIdx.x;   // float4 index
    int h4  = i % H4;
    int row = i / H4;
    int s   = row & (S_ - 1);

    float4 cur = ((const float4*)hidden)[i];
    float4 sh  = make_float4(0.f, 0.f, 0.f, 0.f);
    if (s != 0) sh = ((const float4*)hidden)[i - H4];

    float4 mk = ((const float4*)tmk)[h4];
    float4 mv = ((const float4*)tmv)[h4];
    float4 mr = ((const float4*)tmr)[h4];

    float dx = cur.x - sh.x, dy = cur.y - sh.y, dz = cur.z - sh.z, dw = cur.w - sh.w;

    float vals[3][4];
    vals[0][0] = fmaf(mk.x, dx, sh.x); vals[0][1] = fmaf(mk.y, dy, sh.y);
    vals[0][2] = fmaf(mk.z, dz, sh.z); vals[0][3] = fmaf(mk.w, dw, sh.w);
    vals[1][0] = fmaf(mv.x, dx, sh.x); vals[1][1] = fmaf(mv.y, dy, sh.y);
    vals[1][2] = fmaf(mv.z, dz, sh.z); vals[1][3] = fmaf(mv.w, dw, sh.w);
    vals[2][0] = fmaf(mr.x, dx, sh.x); vals[2][1] = fmaf(mr.y, dy, sh.y);
    vals[2][2] = fmaf(mr.z, dz, sh.z); vals[2][3] = fmaf(mr.w, dw, sh.w);

    __half2* dst[3] = {(__half2*)g_xk, (__half2*)g_xv, (__half2*)g_xr};
#pragma unroll
    for (int t = 0; t < 3; ++t) {
        dst[t][2 * i]     = __half2(__float2half_rn(vals[t][0]), __float2half_rn(vals[t][1]));
        dst[t][2 * i + 1] = __half2(__float2half_rn(vals[t][2]), __float2half_rn(vals[t][3]));
    }
}

// ============================================================================
// HMMA GEMM core, fp16 single-pass, K = 2048.
// CTA 128x128, 512 threads / 16 warps (4x4), warp tile 32x32.
// BK=64 per stage (SW128), ldmatrix.x4, 3-stage cp.async pipeline.
// __launch_bounds__(512, 2): <=64 regs -> 2 CTAs/SM.
// ============================================================================
#define NST 3
#define BKS 64
#define STGB (128 * 128)                // bytes per matrix per stage
#define NSTEP (K_ / BKS)                // 32

__device__ __forceinline__ void gemm_core(
    const __half* __restrict__ A, const __half* __restrict__ Bf,
    float* __restrict__ C, bool sig, char* sm, int bx, int by) {

    const int tid  = threadIdx.x;
    const int wid  = tid >> 5;
    const int lane = tid & 31;
    const int wm   = wid >> 2;      // 0..3
    const int wn   = wid & 3;       // 0..3
    const int g    = lane >> 2;
    const int t4   = lane & 3;

    const int rowA0 = by * 128;
    const int rowB0 = bx * 128;

    const uint32_t sA0 = smem_u32(sm);
    const uint32_t sB0 = sA0 + NST * STGB;

    auto load_stage = [&](int st, int slot) {
        int k0 = st * BKS;
#pragma unroll
        for (int i = 0; i < 2; ++i) {
            int id = i * 512 + tid;
            int row = id >> 3, c = id & 7;
            uint32_t sw = swz(row * 128 + c * 16);
            cpasync16(sA0 + slot * STGB + sw, A + (size_t)(rowA0 + row) * K_ + k0 + c * 8);
        }
#pragma unroll
        for (int i = 0; i < 2; ++i) {
            int id = i * 512 + tid;
            int row = id >> 3, c = id & 7;
            uint32_t sw = swz(row * 128 + c * 16);
            cpasync16(sB0 + slot * STGB + sw, Bf + (size_t)(rowB0 + row) * K_ + k0 + c * 8);
        }
    };

    const int tsel = lane >> 3;
    const int rin  = lane & 7;
    const int aRowBase = wm * 32 + (tsel & 1) * 8 + rin;
    const int aColBase = (tsel >> 1) * 16;
    const int bRowBase = wn * 32 + (tsel >> 1) * 8 + rin;
    const int bColBase = (tsel & 1) * 16;

    float acc[2][4][4];
#pragma unroll
    for (int i = 0; i < 2; ++i)
#pragma unroll
        for (int j = 0; j < 4; ++j)
#pragma unroll
            for (int r = 0; r < 4; ++r) acc[i][j][r] = 0.f;

    load_stage(0, 0); cp_commit();
    load_stage(1, 1); cp_commit();

    for (int kt = 0; kt < NSTEP; ++kt) {
        const int slot = kt % NST;
        if (kt + 1 < NSTEP) cp_wait<1>(); else cp_wait<0>();
        __syncthreads();

        if (kt + 2 < NSTEP) { load_stage(kt + 2, (kt + 2) % NST); cp_commit(); }

        const uint32_t aBase = sA0 + slot * STGB;
        const uint32_t bBase = sB0 + slot * STGB;

#pragma unroll
        for (int kc = 0; kc < 4; ++kc) {
            uint32_t afr[2][4];
#pragma unroll
            for (int mt = 0; mt < 2; ++mt)
                ldsm4(afr[mt], aBase + swz((aRowBase + mt * 16) * 128 + kc * 32 + aColBase));
            uint32_t bfr[2][4];
#pragma unroll
            for (int np = 0; np < 2; ++np)
                ldsm4(bfr[np], bBase + swz((bRowBase + np * 16) * 128 + kc * 32 + bColBase));
#pragma unroll
            for (int mt = 0; mt < 2; ++mt)
#pragma unroll
                for (int nt = 0; nt < 4; ++nt)
                    mma16816(acc[mt][nt], afr[mt], &bfr[nt >> 1][(nt & 1) * 2]);
        }
    }

    // epilogue
#pragma unroll
    for (int mt = 0; mt < 2; ++mt) {
        size_t row = (size_t)rowA0 + wm * 32 + mt * 16 + g;
#pragma unroll
        for (int nt = 0; nt < 4; ++nt) {
            int col = rowB0 + wn * 32 + nt * 8 + 2 * t4;
            float2 lo = make_float2(acc[mt][nt][0], acc[mt][nt][1]);
            float2 hi = make_float2(acc[mt][nt][2], acc[mt][nt][3]);
            if (sig) {
                lo.x = 1.f / (1.f + __expf(-lo.x)); lo.y = 1.f / (1.f + __expf(-lo.y));
                hi.x = 1.f / (1.f + __expf(-hi.x)); hi.y = 1.f / (1.f + __expf(-hi.y));
            }
            *(float2*)(C + row * N_ + col) = lo;
            *(float2*)(C + (row + 8) * N_ + col) = hi;
        }
    }
}

// Fused projection GEMMs: blockIdx.z selects k/v/r
__global__ __launch_bounds__(512, 2) void gemm_proj() {
    extern __shared__ char sm[];
    const int z = blockIdx.z;
    if (z == 0)
        gemm_core(g_xk, g_wf[0], g_k, false, sm, blockIdx.x, blockIdx.y);
    else if (z == 1)
        gemm_core(g_xv, g_wf[1], g_v, false, sm, blockIdx.x, blockIdx.y);
    else
        gemm_core(g_xr, g_wf[2], g_r, true, sm, blockIdx.x, blockIdx.y);
}

// Output GEMM
__global__ __launch_bounds__(512, 2) void gemm_out(float* __restrict__ out) {
    extern __shared__ char sm[];
    gemm_core(g_y, g_wf[3], out, false, sm, blockIdx.x, blockIdx.y);
}

// ============================================================================
// WKV scan with 16-deep register prefetch pipeline. One thread per (b,d).
// ============================================================================
#define WKV_P 16

__global__ __launch_bounds__(32) void wkv_kernel(const float* __restrict__ time_decay,
                                                 const float* __restrict__ time_first) {
    int t = blockIdx.x * blockDim.x + threadIdx.x;
    int b = t >> 11;
    int d = t & (H_ - 1);

    float w  = -__expf(time_decay[d]);
    float tf = time_first[d];

    float num = 0.f, den = 0.f, mx = -1e38f;
    const size_t base = (size_t)b * S_ * H_ + d;

    float kb[WKV_P], vb[WKV_P], rb[WKV_P];
#pragma unroll
    for (int i = 0; i < WKV_P; ++i) {
        size_t p = base + (size_t)i * H_;
        kb[i] = g_k[p]; vb[i] = g_v[p]; rb[i] = g_r[p];
    }

    for (int s0 = 0; s0 < S_; s0 += WKV_P) {
#pragma unroll
        for (int u = 0; u < WKV_P; ++u) {
            const int s = s0 + u;
            const size_t idx = base + (size_t)s * H_;

            float k = kb[u], v = vb[u], r = rb[u];
            if (s + WKV_P < S_) {
                size_t p = idx + (size_t)WKV_P * H_;
                kb[u] = g_k[p]; vb[u] = g_v[p]; rb[u] = g_r[p];
            }

            float ktf = k + tf;
            float mo  = fmaxf(mx, ktf);
            float e1  = __expf(mx - mo);
            float e2  = __expf(ktf - mo);
            float out = __fdividef(e1 * num + e2 * v, e1 * den + e2);
            g_y[idx] = __float2half_rn(r * out);

            float mw  = mx + w;
            float mn  = fmaxf(mw, k);
            float e1n = __expf(mw - mn);
            float e2n = __expf(k - mn);
            num = e1n * num + e2n * v;
            den = e1n * den + e2n;
            mx  = mn;
        }
    }
}

// ============================================================================
// Launch
// ============================================================================
extern "C" void kernel_launch(void* const* d_in, const int* in_sizes, int n_in,
                              void* d_out, int out_size) {
    const float* hidden     = (const float*)d_in[0];
    const float* time_decay = (const float*)d_in[1];
    const float* time_first = (const float*)d_in[2];
    const float* tmk        = (const float*)d_in[3];
    const float* tmv        = (const float*)d_in[4];
    const float* tmr        = (const float*)d_in[5];
    const float* Wk         = (const float*)d_in[6];
    const float* Wv         = (const float*)d_in[7];
    const float* Wr         = (const float*)d_in[8];
    const float* Wo         = (const float*)d_in[9];
    float* out              = (float*)d_out;

    const int shm = 2 * NST * STGB;   // 96 KB
    cudaFuncSetAttribute(gemm_proj, cudaFuncAttributeMaxDynamicSharedMemorySize, shm);
    cudaFuncSetAttribute(gemm_out,  cudaFuncAttributeMaxDynamicSharedMemorySize, shm);

    // 0) weight conversion to fp16
    {
        dim3 g((N_ * K_ / 4) / 256, 4);
        convw_all<<<g, 256>>>(Wk, Wv, Wr, Wo);
    }

    // 1) time-shift mix (fp32 -> fp16)
    mix_kernel<<<(M_ * H_ / 4) / 256, 256>>>(hidden, tmk, tmv, tmr);

    // 2) fused projection GEMMs (k, v, r)
    dim3 gg(N_ / 128, M_ / 128, 3);   // (16, 64, 3)
    gemm_proj<<<gg, 512, shm>>>();

    // 3) WKV scan (writes y fp16)
    wkv_kernel<<<(B_ * H_) / 32, 32>>>(time_decay, time_first);

    // 4) output GEMM
    dim3 go(N_ / 128, M_ / 128);
    gemm_out<<<go, 512, shm>>>(out);
}

// round 10
// speedup vs baseline: 6.2322x; 1.2696x over previous
#include <cuda_runtime.h>
#include <cuda_fp16.h>
#include <cstdint>

// Shapes: B=4, S=2048, H=D=2048
#define B_ 4
#define S_ 2048
#define H_ 2048
#define M_ (B_ * S_)   // 8192
#define N_ H_
#define K_ H_
#define CH_ (B_ * H_)  // 8192 channels

// WKV chunking
#define NCH 32
#define TCH (S_ / NCH)   // 64

// ---------------- scratch (static device arrays, no allocation) -------------
__device__ __half g_xk[(size_t)M_ * H_];
__device__ __half g_xv[(size_t)M_ * H_];
__device__ __half g_xr[(size_t)M_ * H_];
__device__ __half g_y [(size_t)M_ * H_];
__device__ __half g_wf[4][(size_t)N_ * K_];
__device__ float g_k[(size_t)M_ * H_];
__device__ float g_v[(size_t)M_ * H_];
__device__ float g_r[(size_t)M_ * H_];
// chunk states + prefixes: [chunk][channel]
__device__ float g_stn[NCH][CH_], g_std[NCH][CH_], g_stm[NCH][CH_];
__device__ float g_pfn[NCH][CH_], g_pfd[NCH][CH_], g_pfm[NCH][CH_];

// ---------------- helpers ----------------
__device__ __forceinline__ uint32_t smem_u32(const void* p) {
    uint32_t a;
    asm("{ .reg .u64 t; cvta.to.shared.u64 t, %1; cvt.u32.u64 %0, t; }"
        : "=r"(a) : "l"(p));
    return a;
}
__device__ __forceinline__ void cpasync16(uint32_t dst, const void* src) {
    asm volatile("cp.async.cg.shared.global [%0], [%1], 16;" :: "r"(dst), "l"(src));
}
__device__ __forceinline__ void cp_commit() {
    asm volatile("cp.async.commit_group;" ::: "memory");
}
template <int N> __device__ __forceinline__ void cp_wait() {
    asm volatile("cp.async.wait_group %0;" :: "n"(N) : "memory");
}
__device__ __forceinline__ void ldsm4(uint32_t* r, uint32_t a) {
    asm volatile("ldmatrix.sync.aligned.m8n8.x4.shared.b16 {%0,%1,%2,%3}, [%4];"
                 : "=r"(r[0]), "=r"(r[1]), "=r"(r[2]), "=r"(r[3]) : "r"(a));
}
__device__ __forceinline__ void mma16816(float* c, const uint32_t* a, const uint32_t* b) {
    asm volatile(
        "mma.sync.aligned.m16n8k16.row.col.f32.f16.f16.f32 "
        "{%0,%1,%2,%3}, {%4,%5,%6,%7}, {%8,%9}, {%0,%1,%2,%3};"
        : "+f"(c[0]), "+f"(c[1]), "+f"(c[2]), "+f"(c[3])
        : "r"(a[0]), "r"(a[1]), "r"(a[2]), "r"(a[3]), "r"(b[0]), "r"(b[1]));
}
__device__ __forceinline__ uint32_t swz(uint32_t off) {   // SW128
    return off ^ ((off >> 3) & 0x70);
}

// ============================================================================
// Convert all four W matrices (fp32) to fp16. grid (4096, 4).
// ============================================================================
__global__ void convw_all(const float* __restrict__ W0, const float* __restrict__ W1,
                          const float* __restrict__ W2, const float* __restrict__ W3) {
    const int widx = blockIdx.y;
    const float* W = (widx == 0) ? W0 : (widx == 1) ? W1 : (widx == 2) ? W2 : W3;
    int i = blockIdx.x * blockDim.x + threadIdx.x;
    float4 w = ((const float4*)W)[i];
    __half2* pf = (__half2*)g_wf[widx];
    pf[2 * i]     = __half2(__float2half_rn(w.x), __float2half_rn(w.y));
    pf[2 * i + 1] = __half2(__float2half_rn(w.z), __float2half_rn(w.w));
}

// ============================================================================
// time-shift mix -> fp16 xk, xv, xr
// ============================================================================
__global__ void mix_kernel(const float* __restrict__ hidden,
                           const float* __restrict__ tmk,
                           const float* __restrict__ tmv,
                           const float* __restrict__ tmr) {
    const int H4 = H_ / 4;
    int i = blockIdx.x * blockDim.x + threadIdx.x;
    int h4  = i % H4;
    int row = i / H4;
    int s   = row & (S_ - 1);

    float4 cur = ((const float4*)hidden)[i];
    float4 sh  = make_float4(0.f, 0.f, 0.f, 0.f);
    if (s != 0) sh = ((const float4*)hidden)[i - H4];

    float4 mk = ((const float4*)tmk)[h4];
    float4 mv = ((const float4*)tmv)[h4];
    float4 mr = ((const float4*)tmr)[h4];

    float dx = cur.x - sh.x, dy = cur.y - sh.y, dz = cur.z - sh.z, dw = cur.w - sh.w;

    float vals[3][4];
    vals[0][0] = fmaf(mk.x, dx, sh.x); vals[0][1] = fmaf(mk.y, dy, sh.y);
    vals[0][2] = fmaf(mk.z, dz, sh.z); vals[0][3] = fmaf(mk.w, dw, sh.w);
    vals[1][0] = fmaf(mv.x, dx, sh.x); vals[1][1] = fmaf(mv.y, dy, sh.y);
    vals[1][2] = fmaf(mv.z, dz, sh.z); vals[1][3] = fmaf(mv.w, dw, sh.w);
    vals[2][0] = fmaf(mr.x, dx, sh.x); vals[2][1] = fmaf(mr.y, dy, sh.y);
    vals[2][2] = fmaf(mr.z, dz, sh.z); vals[2][3] = fmaf(mr.w, dw, sh.w);

    __half2* dst[3] = {(__half2*)g_xk, (__half2*)g_xv, (__half2*)g_xr};
#pragma unroll
    for (int t = 0; t < 3; ++t) {
        dst[t][2 * i]     = __half2(__float2half_rn(vals[t][0]), __float2half_rn(vals[t][1]));
        dst[t][2 * i + 1] = __half2(__float2half_rn(vals[t][2]), __float2half_rn(vals[t][3]));
    }
}

// ============================================================================
// HMMA GEMM core (fp16, K=2048) — unchanged from R9.
// ============================================================================
#define NST 3
#define BKS 64
#define STGB (128 * 128)
#define NSTEP (K_ / BKS)                // 32

__device__ __forceinline__ void gemm_core(
    const __half* __restrict__ A, const __half* __restrict__ Bf,
    float* __restrict__ C, bool sig, char* sm, int bx, int by) {

    const int tid  = threadIdx.x;
    const int wid  = tid >> 5;
    const int lane = tid & 31;
    const int wm   = wid >> 2;
    const int wn   = wid & 3;
    const int g    = lane >> 2;
    const int t4   = lane & 3;

    const int rowA0 = by * 128;
    const int rowB0 = bx * 128;

    const uint32_t sA0 = smem_u32(sm);
    const uint32_t sB0 = sA0 + NST * STGB;

    auto load_stage = [&](int st, int slot) {
        int k0 = st * BKS;
#pragma unroll
        for (int i = 0; i < 2; ++i) {
            int id = i * 512 + tid;
            int row = id >> 3, c = id & 7;
            uint32_t sw = swz(row * 128 + c * 16);
            cpasync16(sA0 + slot * STGB + sw, A + (size_t)(rowA0 + row) * K_ + k0 + c * 8);
        }
#pragma unroll
        for (int i = 0; i < 2; ++i) {
            int id = i * 512 + tid;
            int row = id >> 3, c = id & 7;
            uint32_t sw = swz(row * 128 + c * 16);
            cpasync16(sB0 + slot * STGB + sw, Bf + (size_t)(rowB0 + row) * K_ + k0 + c * 8);
        }
    };

    const int tsel = lane >> 3;
    const int rin  = lane & 7;
    const int aRowBase = wm * 32 + (tsel & 1) * 8 + rin;
    const int aColBase = (tsel >> 1) * 16;
    const int bRowBase = wn * 32 + (tsel >> 1) * 8 + rin;
    const int bColBase = (tsel & 1) * 16;

    float acc[2][4][4];
#pragma unroll
    for (int i = 0; i < 2; ++i)
#pragma unroll
        for (int j = 0; j < 4; ++j)
#pragma unroll
            for (int r = 0; r < 4; ++r) acc[i][j][r] = 0.f;

    load_stage(0, 0); cp_commit();
    load_stage(1, 1); cp_commit();

    for (int kt = 0; kt < NSTEP; ++kt) {
        const int slot = kt % NST;
        if (kt + 1 < NSTEP) cp_wait<1>(); else cp_wait<0>();
        __syncthreads();

        if (kt + 2 < NSTEP) { load_stage(kt + 2, (kt + 2) % NST); cp_commit(); }

        const uint32_t aBase = sA0 + slot * STGB;
        const uint32_t bBase = sB0 + slot * STGB;

#pragma unroll
        for (int kc = 0; kc < 4; ++kc) {
            uint32_t afr[2][4];
#pragma unroll
            for (int mt = 0; mt < 2; ++mt)
                ldsm4(afr[mt], aBase + swz((aRowBase + mt * 16) * 128 + kc * 32 + aColBase));
            uint32_t bfr[2][4];
#pragma unroll
            for (int np = 0; np < 2; ++np)
                ldsm4(bfr[np], bBase + swz((bRowBase + np * 16) * 128 + kc * 32 + bColBase));
#pragma unroll
            for (int mt = 0; mt < 2; ++mt)
#pragma unroll
                for (int nt = 0; nt < 4; ++nt)
                    mma16816(acc[mt][nt], afr[mt], &bfr[nt >> 1][(nt & 1) * 2]);
        }
    }

#pragma unroll
    for (int mt = 0; mt < 2; ++mt) {
        size_t row = (size_t)rowA0 + wm * 32 + mt * 16 + g;
#pragma unroll
        for (int nt = 0; nt < 4; ++nt) {
            int col = rowB0 + wn * 32 + nt * 8 + 2 * t4;
            float2 lo = make_float2(acc[mt][nt][0], acc[mt][nt][1]);
            float2 hi = make_float2(acc[mt][nt][2], acc[mt][nt][3]);
            if (sig) {
                lo.x = 1.f / (1.f + __expf(-lo.x)); lo.y = 1.f / (1.f + __expf(-lo.y));
                hi.x = 1.f / (1.f + __expf(-hi.x)); hi.y = 1.f / (1.f + __expf(-hi.y));
            }
            *(float2*)(C + row * N_ + col) = lo;
            *(float2*)(C + (row + 8) * N_ + col) = hi;
        }
    }
}

__global__ __launch_bounds__(512, 2) void gemm_proj() {
    extern __shared__ char sm[];
    const int z = blockIdx.z;
    if (z == 0)
        gemm_core(g_xk, g_wf[0], g_k, false, sm, blockIdx.x, blockIdx.y);
    else if (z == 1)
        gemm_core(g_xv, g_wf[1], g_v, false, sm, blockIdx.x, blockIdx.y);
    else
        gemm_core(g_xr, g_wf[2], g_r, true, sm, blockIdx.x, blockIdx.y);
}

__global__ __launch_bounds__(512, 2) void gemm_out(float* __restrict__ out) {
    extern __shared__ char sm[];
    gemm_core(g_y, g_wf[3], out, false, sm, blockIdx.x, blockIdx.y);
}

// ============================================================================
// WKV chunked scan.
// Pass 1: per (channel, chunk) local state from zero-init.
// Pass 2: per channel, sequential combine over 32 chunks -> prefix states.
// Pass 3: per (channel, chunk) replay from prefix, emit outputs.
// ============================================================================
__global__ __launch_bounds__(256) void wkv_pass1(const float* __restrict__ time_decay) {
    const int c = blockIdx.y;                                   // chunk
    const int t = blockIdx.x * blockDim.x + threadIdx.x;        // channel
    const int b = t >> 11;
    const int d = t & (H_ - 1);
    const float w = -__expf(time_decay[d]);

    float num = 0.f, den = 0.f, mx = -1e38f;
    size_t idx = (size_t)b * S_ * H_ + (size_t)c * TCH * H_ + d;
#pragma unroll 4
    for (int s = 0; s < TCH; ++s, idx += H_) {
        float k = g_k[idx];
        float v = g_v[idx];
        float mw  = mx + w;
        float mn  = fmaxf(mw, k);
        float e1  = __expf(mw - mn);
        float e2  = __expf(k - mn);
        num = e1 * num + e2 * v;
        den = e1 * den + e2;
        mx  = mn;
    }
    g_stn[c][t] = num; g_std[c][t] = den; g_stm[c][t] = mx;
}

__global__ __launch_bounds__(256) void wkv_pass2(const float* __restrict__ time_decay) {
    const int t = blockIdx.x * blockDim.x + threadIdx.x;        // channel
    const int d = t & (H_ - 1);
    const float Tw = -__expf(time_decay[d]) * (float)TCH;

    float num = 0.f, den = 0.f, mx = -1e38f;
#pragma unroll
    for (int c = 0; c < NCH; ++c) {
        g_pfn[c][t] = num; g_pfd[c][t] = den; g_pfm[c][t] = mx;
        // combine(decay_T(state), chunk_c)
        float m1 = mx + Tw;
        float n2 = g_stn[c][t], d2 = g_std[c][t], m2 = g_stm[c][t];
        float mm = fmaxf(m1, m2);
        float e1 = __expf(m1 - mm);
        float e2 = __expf(m2 - mm);
        num = e1 * num + e2 * n2;
        den = e1 * den + e2 * d2;
        mx  = mm;
    }
}

__global__ __launch_bounds__(256) void wkv_pass3(const float* __restrict__ time_decay,
                                                 const float* __restrict__ time_first) {
    const int c = blockIdx.y;
    const int t = blockIdx.x * blockDim.x + threadIdx.x;
    const int b = t >> 11;
    const int d = t & (H_ - 1);
    const float w  = -__expf(time_decay[d]);
    const float tf = time_first[d];

    float num = g_pfn[c][t], den = g_pfd[c][t], mx = g_pfm[c][t];
    size_t idx = (size_t)b * S_ * H_ + (size_t)c * TCH * H_ + d;
#pragma unroll 4
    for (int s = 0; s < TCH; ++s, idx += H_) {
        float k = g_k[idx];
        float v = g_v[idx];
        float r = g_r[idx];

        float ktf = k + tf;
        float mo  = fmaxf(mx, ktf);
        float e1  = __expf(mx - mo);
        float e2  = __expf(ktf - mo);
        float out = __fdividef(e1 * num + e2 * v, e1 * den + e2);
        g_y[idx] = __float2half_rn(r * out);

        float mw  = mx + w;
        float mn  = fmaxf(mw, k);
        float e1n = __expf(mw - mn);
        float e2n = __expf(k - mn);
        num = e1n * num + e2n * v;
        den = e1n * den + e2n;
        mx  = mn;
    }
}

// ============================================================================
// Launch
// ============================================================================
extern "C" void kernel_launch(void* const* d_in, const int* in_sizes, int n_in,
                              void* d_out, int out_size) {
    const float* hidden     = (const float*)d_in[0];
    const float* time_decay = (const float*)d_in[1];
    const float* time_first = (const float*)d_in[2];
    const float* tmk        = (const float*)d_in[3];
    const float* tmv        = (const float*)d_in[4];
    const float* tmr        = (const float*)d_in[5];
    const float* Wk         = (const float*)d_in[6];
    const float* Wv         = (const float*)d_in[7];
    const float* Wr         = (const float*)d_in[8];
    const float* Wo         = (const float*)d_in[9];
    float* out              = (float*)d_out;

    const int shm = 2 * NST * STGB;   // 96 KB
    cudaFuncSetAttribute(gemm_proj, cudaFuncAttributeMaxDynamicSharedMemorySize, shm);
    cudaFuncSetAttribute(gemm_out,  cudaFuncAttributeMaxDynamicSharedMemorySize, shm);

    // 0) weight conversion to fp16
    {
        dim3 g((N_ * K_ / 4) / 256, 4);
        convw_all<<<g, 256>>>(Wk, Wv, Wr, Wo);
    }

    // 1) time-shift mix (fp32 -> fp16)
    mix_kernel<<<(M_ * H_ / 4) / 256, 256>>>(hidden, tmk, tmv, tmr);

    // 2) fused projection GEMMs (k, v, r)
    dim3 gg(N_ / 128, M_ / 128, 3);
    gemm_proj<<<gg, 512, shm>>>();

    // 3) WKV chunked scan
    {
        dim3 gp(CH_ / 256, NCH);
        wkv_pass1<<<gp, 256>>>(time_decay);
        wkv_pass2<<<CH_ / 256, 256>>>(time_decay);
        wkv_pass3<<<gp, 256>>>(time_decay, time_first);
    }

    // 4) output GEMM
    dim3 go(N_ / 128, M_ / 128);
    gemm_out<<<go, 512, shm>>>(out);
}